// round 7
// baseline (speedup 1.0000x reference)
#include <cuda_runtime.h>
#include <math_constants.h>

#define BB 8
#define NN 50000
#define LL 512
#define RR 5
#define GPB 256                 // blocks per batch in the fused kernel
#define WPB 8                   // warps per block
#define WARPS_PER_BATCH (GPB * WPB)   // 2048

#define H1 200
#define H2 100
#define CC 2

// partial top/bot candidates: one sorted 5+5 set per block per batch
__device__ float g_part_top[BB * GPB * RR];   // sorted descending per 5-group
__device__ float g_part_bot[BB * GPB * RR];   // sorted ascending per 5-group

// ---------------------------------------------------------------------------
// sorted-insertion helpers
// ---------------------------------------------------------------------------
__device__ __forceinline__ void insert_max(float* arr, float v) {
    if (v > arr[RR - 1]) {
        arr[RR - 1] = v;
#pragma unroll
        for (int j = RR - 1; j > 0; j--) {
            if (arr[j] > arr[j - 1]) {
                float t = arr[j]; arr[j] = arr[j - 1]; arr[j - 1] = t;
            }
        }
    }
}
__device__ __forceinline__ void insert_min(float* arr, float v) {
    if (v < arr[RR - 1]) {
        arr[RR - 1] = v;
#pragma unroll
        for (int j = RR - 1; j > 0; j--) {
            if (arr[j] < arr[j - 1]) {
                float t = arr[j]; arr[j] = arr[j - 1]; arr[j - 1] = t;
            }
        }
    }
}

// merge two sorted-descending 5-lists -> top 5
__device__ __forceinline__ void merge_desc5(const float* a, const float* b, float* o) {
    int i = 0, j = 0;
#pragma unroll
    for (int k = 0; k < RR; k++) {
        float av = a[i], bv = b[j];
        bool ta = (av >= bv);
        o[k] = ta ? av : bv;
        i += ta; j += !ta;
    }
}
// merge two sorted-ascending 5-lists -> bottom 5
__device__ __forceinline__ void merge_asc5(const float* a, const float* b, float* o) {
    int i = 0, j = 0;
#pragma unroll
    for (int k = 0; k < RR; k++) {
        float av = a[i], bv = b[j];
        bool ta = (av <= bv);
        o[k] = ta ? av : bv;
        i += ta; j += !ta;
    }
}

// ---------------------------------------------------------------------------
// Kernel A: scores + running top-5/bot-5. grid = (GPB, BB), 256 threads.
// EXACT R4 version — proven 117.5us @ 88.6% DRAM, regs=32. Do not touch.
// ---------------------------------------------------------------------------
__global__ __launch_bounds__(256) void chowder_scores_topk_kernel(
    const float* __restrict__ x,
    const float* __restrict__ conv_w,
    const float* __restrict__ conv_b)
{
    __shared__ float4 ws[LL / 4];
    __shared__ float stop[WPB * RR];
    __shared__ float sbot[WPB * RR];

    const int tid  = threadIdx.x;
    const int warp = tid >> 5;
    const int lane = tid & 31;
    const int b    = blockIdx.y;

    for (int i = tid; i < LL / 4; i += blockDim.x)
        ws[i] = reinterpret_cast<const float4*>(conv_w)[i];
    __syncthreads();

    float4 w0  = ws[0 * 32 + lane];
    float4 w1r = ws[1 * 32 + lane];
    float4 w2r = ws[2 * 32 + lane];
    float4 w3r = ws[3 * 32 + lane];

    const int gw = blockIdx.x * WPB + warp;
    const float cb = conv_b[0];
    const float* __restrict__ xb = x + (long long)b * NN * LL;

    float top[RR], bot[RR];
#pragma unroll
    for (int i = 0; i < RR; i++) { top[i] = -CUDART_INF_F; bot[i] = CUDART_INF_F; }

    for (int inst = gw; inst < NN; inst += WARPS_PER_BATCH) {
        const float4* __restrict__ xp =
            reinterpret_cast<const float4*>(xb + (long long)inst * LL);

        float4 v0 = xp[0 * 32 + lane];
        float4 v1 = xp[1 * 32 + lane];
        float4 v2 = xp[2 * 32 + lane];
        float4 v3 = xp[3 * 32 + lane];

        float acc = 0.0f;
        acc = fmaf(v0.x, w0.x,  acc); acc = fmaf(v0.y, w0.y,  acc);
        acc = fmaf(v0.z, w0.z,  acc); acc = fmaf(v0.w, w0.w,  acc);
        acc = fmaf(v1.x, w1r.x, acc); acc = fmaf(v1.y, w1r.y, acc);
        acc = fmaf(v1.z, w1r.z, acc); acc = fmaf(v1.w, w1r.w, acc);
        acc = fmaf(v2.x, w2r.x, acc); acc = fmaf(v2.y, w2r.y, acc);
        acc = fmaf(v2.z, w2r.z, acc); acc = fmaf(v2.w, w2r.w, acc);
        acc = fmaf(v3.x, w3r.x, acc); acc = fmaf(v3.y, w3r.y, acc);
        acc = fmaf(v3.z, w3r.z, acc); acc = fmaf(v3.w, w3r.w, acc);

#pragma unroll
        for (int o = 16; o; o >>= 1)
            acc += __shfl_xor_sync(0xffffffff, acc, o);

        if (lane == 0) {
            float v = acc + cb;
            insert_max(top, v);
            insert_min(bot, v);
        }
    }

    if (lane == 0) {
#pragma unroll
        for (int j = 0; j < RR; j++) {
            stop[warp * RR + j] = top[j];
            sbot[warp * RR + j] = bot[j];
        }
    }
    __syncthreads();

    if (tid == 0) {
        float ft[RR], fb[RR];
#pragma unroll
        for (int i = 0; i < RR; i++) { ft[i] = -CUDART_INF_F; fb[i] = CUDART_INF_F; }
        for (int i = 0; i < WPB * RR; i++) {
            insert_max(ft, stop[i]);
            insert_min(fb, sbot[i]);
        }
        float* pt = g_part_top + ((long long)b * GPB + blockIdx.x) * RR;
        float* pb = g_part_bot + ((long long)b * GPB + blockIdx.x) * RR;
#pragma unroll
        for (int j = 0; j < RR; j++) { pt[j] = ft[j]; pb[j] = fb[j]; }
    }
}

// ---------------------------------------------------------------------------
// Kernel B: warp-specialized merge + MLP collapse. grid = BB, 256 threads.
//   warps 0-3 (tid 0..127):  stage partials + 8-level tournament  (bar 1)
//   warps 4-7 (tid 128..255): collapse W_eff = W1@W2@W3, b_eff     (bar 2)
// Both halves run concurrently; final __syncthreads; 20-FMA matvec.
// ---------------------------------------------------------------------------
__global__ __launch_bounds__(256) void chowder_merge_mlp_kernel(
    const float* __restrict__ w1, const float* __restrict__ b1,
    const float* __restrict__ w2, const float* __restrict__ b2,
    const float* __restrict__ w3, const float* __restrict__ b3,
    float* __restrict__ out)
{
    const int b   = blockIdx.x;
    const int tid = threadIdx.x;

    __shared__ float stop[GPB * RR];      // 5 KB
    __shared__ float sbot[GPB * RR];      // 5 KB
    __shared__ float cat[2 * RR];
    __shared__ float sW12[2 * RR * H2];   // 4 KB   W1@W2
    __shared__ float sb12[H2];
    __shared__ float sWe[2 * RR * CC];
    __shared__ float sbe[CC];

    if (tid < 128) {
        // ========== tournament half ==========
        const float* pt = g_part_top + (long long)b * GPB * RR;
        const float* pb = g_part_bot + (long long)b * GPB * RR;
#pragma unroll
        for (int i = tid; i < GPB * RR; i += 128) {
            stop[i] = pt[i];
            sbot[i] = pb[i];
        }
        asm volatile("bar.sync 1, 128;" ::: "memory");

        for (int cnt = GPB; cnt > 1; cnt >>= 1) {
            int half = cnt >> 1;
            if (tid < half) {
                float a[RR], c[RR], o[RR];
#pragma unroll
                for (int j = 0; j < RR; j++) { a[j] = stop[tid * RR + j]; c[j] = stop[(tid + half) * RR + j]; }
                merge_desc5(a, c, o);
#pragma unroll
                for (int j = 0; j < RR; j++) stop[tid * RR + j] = o[j];

#pragma unroll
                for (int j = 0; j < RR; j++) { a[j] = sbot[tid * RR + j]; c[j] = sbot[(tid + half) * RR + j]; }
                merge_asc5(a, c, o);
#pragma unroll
                for (int j = 0; j < RR; j++) sbot[tid * RR + j] = o[j];
            }
            asm volatile("bar.sync 1, 128;" ::: "memory");
        }

        // cat = [min ascending, max descending]
        if (tid < RR)          cat[tid] = sbot[tid];
        else if (tid < 2 * RR) cat[tid] = stop[tid - RR];
    } else {
        // ========== MLP collapse half ==========
        const int ct = tid - 128;
        if (ct < H2) {
            const int o = ct;
            float acc[2 * RR];
            float accb = 0.0f;
#pragma unroll
            for (int i = 0; i < 2 * RR; i++) acc[i] = 0.0f;
#pragma unroll 2
            for (int k = 0; k < H1; k++) {
                float wv = w2[k * H2 + o];          // coalesced across o
#pragma unroll
                for (int i = 0; i < 2 * RR; i++)
                    acc[i] = fmaf(w1[i * H1 + k], wv, acc[i]);   // broadcast
                accb = fmaf(b1[k], wv, accb);
            }
#pragma unroll
            for (int i = 0; i < 2 * RR; i++) sW12[i * H2 + o] = acc[i];
            sb12[o] = accb + b2[o];
        }
        asm volatile("bar.sync 2, 128;" ::: "memory");

        // W_eff[i][c] and b_eff[c] from shared
        if (ct < 2 * RR * CC) {
            const int i = ct / CC, c = ct % CC;
            float a = 0.0f;
            for (int o = 0; o < H2; o++)
                a = fmaf(sW12[i * H2 + o], w3[o * CC + c], a);
            sWe[i * CC + c] = a;
        }
        if (ct >= 32 && ct < 32 + CC) {
            const int c = ct - 32;
            float a = b3[c];
            for (int o = 0; o < H2; o++)
                a = fmaf(sb12[o], w3[o * CC + c], a);
            sbe[c] = a;
        }
    }

    __syncthreads();

    // out = cat @ W_eff + b_eff  (20 FMAs)
    if (tid < CC) {
        float a = sbe[tid];
#pragma unroll
        for (int i = 0; i < 2 * RR; i++)
            a = fmaf(cat[i], sWe[i * CC + tid], a);
        out[b * CC + tid] = a;
    }
}

// ---------------------------------------------------------------------------
extern "C" void kernel_launch(void* const* d_in, const int* in_sizes, int n_in,
                              void* d_out, int out_size)
{
    const float* x      = (const float*)d_in[0];
    const float* conv_w = (const float*)d_in[1];
    const float* conv_b = (const float*)d_in[2];
    const float* w1     = (const float*)d_in[3];
    const float* b1     = (const float*)d_in[4];
    const float* w2     = (const float*)d_in[5];
    const float* b2     = (const float*)d_in[6];
    const float* w3     = (const float*)d_in[7];
    const float* b3     = (const float*)d_in[8];
    float* out          = (float*)d_out;

    dim3 grid(GPB, BB);
    chowder_scores_topk_kernel<<<grid, 256>>>(x, conv_w, conv_b);
    chowder_merge_mlp_kernel<<<BB, 256>>>(w1, b1, w2, b2, w3, b3, out);
}

// round 8
// speedup vs baseline: 1.3499x; 1.3499x over previous
#include <cuda_runtime.h>
#include <math_constants.h>

#define BB 8
#define NN 50000
#define LL 512
#define RR 5
#define GPB 256                 // blocks per batch in the fused kernel
#define WPB 8                   // warps per block
#define WARPS_PER_BATCH (GPB * WPB)   // 2048

#define H1 200
#define H2 100
#define CC 2
#define TK 40                   // w2 k-tile rows (5 tiles cover H1=200)

// partial top/bot candidates: one sorted 5+5 set per block per batch
__device__ float g_part_top[BB * GPB * RR];   // sorted descending per 5-group
__device__ float g_part_bot[BB * GPB * RR];   // sorted ascending per 5-group

// ---------------------------------------------------------------------------
// sorted-insertion helpers
// ---------------------------------------------------------------------------
__device__ __forceinline__ void insert_max(float* arr, float v) {
    if (v > arr[RR - 1]) {
        arr[RR - 1] = v;
#pragma unroll
        for (int j = RR - 1; j > 0; j--) {
            if (arr[j] > arr[j - 1]) {
                float t = arr[j]; arr[j] = arr[j - 1]; arr[j - 1] = t;
            }
        }
    }
}
__device__ __forceinline__ void insert_min(float* arr, float v) {
    if (v < arr[RR - 1]) {
        arr[RR - 1] = v;
#pragma unroll
        for (int j = RR - 1; j > 0; j--) {
            if (arr[j] < arr[j - 1]) {
                float t = arr[j]; arr[j] = arr[j - 1]; arr[j - 1] = t;
            }
        }
    }
}

// merge two sorted-descending 5-lists -> top 5
__device__ __forceinline__ void merge_desc5(const float* a, const float* b, float* o) {
    int i = 0, j = 0;
#pragma unroll
    for (int k = 0; k < RR; k++) {
        float av = a[i], bv = b[j];
        bool ta = (av >= bv);
        o[k] = ta ? av : bv;
        i += ta; j += !ta;
    }
}
// merge two sorted-ascending 5-lists -> bottom 5
__device__ __forceinline__ void merge_asc5(const float* a, const float* b, float* o) {
    int i = 0, j = 0;
#pragma unroll
    for (int k = 0; k < RR; k++) {
        float av = a[i], bv = b[j];
        bool ta = (av <= bv);
        o[k] = ta ? av : bv;
        i += ta; j += !ta;
    }
}

// ---------------------------------------------------------------------------
// Kernel A: scores + running top-5/bot-5. grid = (GPB, BB), 256 threads.
// EXACT R4 version — proven 117.5us @ 88.6% DRAM, regs=32. Do not touch.
// ---------------------------------------------------------------------------
__global__ __launch_bounds__(256) void chowder_scores_topk_kernel(
    const float* __restrict__ x,
    const float* __restrict__ conv_w,
    const float* __restrict__ conv_b)
{
    __shared__ float4 ws[LL / 4];
    __shared__ float stop[WPB * RR];
    __shared__ float sbot[WPB * RR];

    const int tid  = threadIdx.x;
    const int warp = tid >> 5;
    const int lane = tid & 31;
    const int b    = blockIdx.y;

    for (int i = tid; i < LL / 4; i += blockDim.x)
        ws[i] = reinterpret_cast<const float4*>(conv_w)[i];
    __syncthreads();

    float4 w0  = ws[0 * 32 + lane];
    float4 w1r = ws[1 * 32 + lane];
    float4 w2r = ws[2 * 32 + lane];
    float4 w3r = ws[3 * 32 + lane];

    const int gw = blockIdx.x * WPB + warp;
    const float cb = conv_b[0];
    const float* __restrict__ xb = x + (long long)b * NN * LL;

    float top[RR], bot[RR];
#pragma unroll
    for (int i = 0; i < RR; i++) { top[i] = -CUDART_INF_F; bot[i] = CUDART_INF_F; }

    for (int inst = gw; inst < NN; inst += WARPS_PER_BATCH) {
        const float4* __restrict__ xp =
            reinterpret_cast<const float4*>(xb + (long long)inst * LL);

        float4 v0 = xp[0 * 32 + lane];
        float4 v1 = xp[1 * 32 + lane];
        float4 v2 = xp[2 * 32 + lane];
        float4 v3 = xp[3 * 32 + lane];

        float acc = 0.0f;
        acc = fmaf(v0.x, w0.x,  acc); acc = fmaf(v0.y, w0.y,  acc);
        acc = fmaf(v0.z, w0.z,  acc); acc = fmaf(v0.w, w0.w,  acc);
        acc = fmaf(v1.x, w1r.x, acc); acc = fmaf(v1.y, w1r.y, acc);
        acc = fmaf(v1.z, w1r.z, acc); acc = fmaf(v1.w, w1r.w, acc);
        acc = fmaf(v2.x, w2r.x, acc); acc = fmaf(v2.y, w2r.y, acc);
        acc = fmaf(v2.z, w2r.z, acc); acc = fmaf(v2.w, w2r.w, acc);
        acc = fmaf(v3.x, w3r.x, acc); acc = fmaf(v3.y, w3r.y, acc);
        acc = fmaf(v3.z, w3r.z, acc); acc = fmaf(v3.w, w3r.w, acc);

#pragma unroll
        for (int o = 16; o; o >>= 1)
            acc += __shfl_xor_sync(0xffffffff, acc, o);

        if (lane == 0) {
            float v = acc + cb;
            insert_max(top, v);
            insert_min(bot, v);
        }
    }

    if (lane == 0) {
#pragma unroll
        for (int j = 0; j < RR; j++) {
            stop[warp * RR + j] = top[j];
            sbot[warp * RR + j] = bot[j];
        }
    }
    __syncthreads();

    if (tid == 0) {
        float ft[RR], fb[RR];
#pragma unroll
        for (int i = 0; i < RR; i++) { ft[i] = -CUDART_INF_F; fb[i] = CUDART_INF_F; }
        for (int i = 0; i < WPB * RR; i++) {
            insert_max(ft, stop[i]);
            insert_min(fb, sbot[i]);
        }
        float* pt = g_part_top + ((long long)b * GPB + blockIdx.x) * RR;
        float* pb = g_part_bot + ((long long)b * GPB + blockIdx.x) * RR;
#pragma unroll
        for (int j = 0; j < RR; j++) { pt[j] = ft[j]; pb[j] = fb[j]; }
    }
}

// ---------------------------------------------------------------------------
// Kernel B: merge + smem-tiled MLP collapse. grid = BB, 256 threads.
//   1. one coalesced staging wave: partials + w1 + b1 + w3 -> smem
//   2. 8-level tournament (smem/registers)
//   3. w2 streamed in 5 coalesced 40x100 smem tiles; 100 threads accumulate
//      W12 = W1@W2 (+ b12) entirely from smem
//   4. fold w3 -> W_eff[10][2], b_eff[2]; 20-FMA matvec
// ---------------------------------------------------------------------------
__global__ __launch_bounds__(256) void chowder_merge_mlp_kernel(
    const float* __restrict__ w1, const float* __restrict__ b1,
    const float* __restrict__ w2, const float* __restrict__ b2,
    const float* __restrict__ w3, const float* __restrict__ b3,
    float* __restrict__ out)
{
    const int b   = blockIdx.x;
    const int tid = threadIdx.x;

    __shared__ float stop[GPB * RR];        // 5 KB
    __shared__ float sbot[GPB * RR];        // 5 KB
    __shared__ float sw1[2 * RR * H1];      // 8 KB   w1 [10][200]
    __shared__ float sb1[H1];               // 800 B
    __shared__ float sw3[H2 * CC];          // 800 B
    __shared__ float sw2t[TK * H2];         // 16 KB  w2 tile [40][100]
    __shared__ float sW12[2 * RR * H2];     // 4 KB
    __shared__ float sb12[H2];
    __shared__ float sWe[2 * RR * CC];
    __shared__ float sbe[CC];
    __shared__ float cat[2 * RR];

    // ---- phase 1: one big coalesced staging wave (all loads independent) ----
    {
        const float* pt = g_part_top + (long long)b * GPB * RR;
        const float* pb = g_part_bot + (long long)b * GPB * RR;
#pragma unroll
        for (int i = tid; i < GPB * RR; i += 256) {
            stop[i] = pt[i];
            sbot[i] = pb[i];
        }
        for (int i = tid; i < 2 * RR * H1; i += 256) sw1[i] = w1[i];
        if (tid < H1)      sb1[tid] = b1[tid];
        if (tid < H2 * CC) sw3[tid] = w3[tid];
    }
    __syncthreads();

    // ---- phase 2: tournament, 256 sorted 5-lists -> 1 ----
    for (int cnt = GPB; cnt > 1; cnt >>= 1) {
        int half = cnt >> 1;
        if (tid < half) {
            float a[RR], c[RR], o[RR];
#pragma unroll
            for (int j = 0; j < RR; j++) { a[j] = stop[tid * RR + j]; c[j] = stop[(tid + half) * RR + j]; }
            merge_desc5(a, c, o);
#pragma unroll
            for (int j = 0; j < RR; j++) stop[tid * RR + j] = o[j];

#pragma unroll
            for (int j = 0; j < RR; j++) { a[j] = sbot[tid * RR + j]; c[j] = sbot[(tid + half) * RR + j]; }
            merge_asc5(a, c, o);
#pragma unroll
            for (int j = 0; j < RR; j++) sbot[tid * RR + j] = o[j];
        }
        __syncthreads();
    }
    if (tid < RR)          cat[tid] = sbot[tid];
    else if (tid < 2 * RR) cat[tid] = stop[tid - RR];

    // ---- phase 3: W12 = W1@W2 via smem-tiled w2 ----
    float acc[2 * RR];
    float accb = 0.0f;
#pragma unroll
    for (int i = 0; i < 2 * RR; i++) acc[i] = 0.0f;

#pragma unroll
    for (int t = 0; t < H1 / TK; t++) {
        __syncthreads();   // protect sw2t reuse
        // cooperative coalesced tile load: 4000 floats / 256 thr ≈ 16 each
        const float* w2t = w2 + t * TK * H2;
#pragma unroll
        for (int i = tid; i < TK * H2; i += 256)
            sw2t[i] = w2t[i];
        __syncthreads();

        if (tid < H2) {
#pragma unroll 8
            for (int k = 0; k < TK; k++) {
                float wv = sw2t[k * H2 + tid];
#pragma unroll
                for (int i = 0; i < 2 * RR; i++)
                    acc[i] = fmaf(sw1[i * H1 + t * TK + k], wv, acc[i]);
                accb = fmaf(sb1[t * TK + k], wv, accb);
            }
        }
    }
    if (tid < H2) {
#pragma unroll
        for (int i = 0; i < 2 * RR; i++) sW12[i * H2 + tid] = acc[i];
        sb12[tid] = accb + b2[tid];
    }
    __syncthreads();

    // ---- phase 4: fold w3 -> W_eff, b_eff ----
    if (tid < 2 * RR * CC) {
        const int i = tid / CC, c = tid % CC;
        float a = 0.0f;
        for (int o = 0; o < H2; o++)
            a = fmaf(sW12[i * H2 + o], sw3[o * CC + c], a);
        sWe[i * CC + c] = a;
    }
    if (tid >= 32 && tid < 32 + CC) {
        const int c = tid - 32;
        float a = b3[c];
        for (int o = 0; o < H2; o++)
            a = fmaf(sb12[o], sw3[o * CC + c], a);
        sbe[c] = a;
    }
    __syncthreads();

    // ---- out = cat @ W_eff + b_eff ----
    if (tid < CC) {
        float a = sbe[tid];
#pragma unroll
        for (int i = 0; i < 2 * RR; i++)
            a = fmaf(cat[i], sWe[i * CC + tid], a);
        out[b * CC + tid] = a;
    }
}

// ---------------------------------------------------------------------------
extern "C" void kernel_launch(void* const* d_in, const int* in_sizes, int n_in,
                              void* d_out, int out_size)
{
    const float* x      = (const float*)d_in[0];
    const float* conv_w = (const float*)d_in[1];
    const float* conv_b = (const float*)d_in[2];
    const float* w1     = (const float*)d_in[3];
    const float* b1     = (const float*)d_in[4];
    const float* w2     = (const float*)d_in[5];
    const float* b2     = (const float*)d_in[6];
    const float* w3     = (const float*)d_in[7];
    const float* b3     = (const float*)d_in[8];
    float* out          = (float*)d_out;

    dim3 grid(GPB, BB);
    chowder_scores_topk_kernel<<<grid, 256>>>(x, conv_w, conv_b);
    chowder_merge_mlp_kernel<<<BB, 256>>>(w1, b1, w2, b2, w3, b3, out);
}